// round 4
// baseline (speedup 1.0000x reference)
#include <cuda_runtime.h>
#include <cstdint>

// ---------------------------------------------------------------------------
// MixedLayerWithArc: per-sample branch-selected 3x3 conv as implicit GEMM
// using mma.sync.m16n8k8 tf32 (plain sm_100 target: no tcgen05).
//
// Per CTA: D[128 co, 128 pix] for one sample, K = 2304 (= ci*9 + tap), 72
// chunks of BK=32. A = RNA-pre-rounded W[arc] (cp.async), B = im2col built
// on the fly (predicated LDG + cvt.rna). fp32 register accumulators.
// ---------------------------------------------------------------------------

static constexpr int KTOT = 2304;
static constexpr int NCH  = KTOT / 32;                 // 72
static constexpr int SMEM_BYTES = 1024 + 4 * 16384;    // pad + 2x(A16K+B16K)

// tf32-rounded copy of W: [4][256][2304] floats = 9.4 MB
__device__ __align__(16) float g_Wtf[4 * 256 * 2304];

#define SWZ(o) ((o) ^ (((o) >> 3) & 0x70))

__device__ __forceinline__ uint32_t smem_u32(const void* p) {
    uint32_t a;
    asm("{ .reg .u64 t; cvta.to.shared.u64 t, %1; cvt.u32.u64 %0, t; }"
        : "=r"(a) : "l"(p));
    return a;
}
__device__ __forceinline__ uint32_t f2tf(float f) {
    uint32_t u;
    asm("cvt.rna.tf32.f32 %0, %1;" : "=r"(u) : "f"(f));
    return u;
}
__device__ __forceinline__ void cp16(uint32_t dst, const void* src) {
    asm volatile("cp.async.cg.shared.global [%0], [%1], 16;"
                 :: "r"(dst), "l"(src) : "memory");
}
__device__ __forceinline__ void sts128(uint32_t a, uint32_t v0, uint32_t v1,
                                       uint32_t v2, uint32_t v3) {
    asm volatile("st.shared.v4.b32 [%0], {%1,%2,%3,%4};"
                 :: "r"(a), "r"(v0), "r"(v1), "r"(v2), "r"(v3) : "memory");
}
__device__ __forceinline__ void ldsm4(uint32_t& r0, uint32_t& r1, uint32_t& r2,
                                      uint32_t& r3, uint32_t a) {
    asm volatile("ldmatrix.sync.aligned.m8n8.x4.shared.b16 {%0,%1,%2,%3}, [%4];"
                 : "=r"(r0), "=r"(r1), "=r"(r2), "=r"(r3) : "r"(a));
}
__device__ __forceinline__ void mma8(float* c, const uint32_t* a,
                                     uint32_t b0, uint32_t b1) {
    asm volatile(
        "mma.sync.aligned.m16n8k8.row.col.f32.tf32.tf32.f32 "
        "{%0,%1,%2,%3}, {%4,%5,%6,%7}, {%8,%9}, {%0,%1,%2,%3};"
        : "+f"(c[0]), "+f"(c[1]), "+f"(c[2]), "+f"(c[3])
        : "r"(a[0]), "r"(a[1]), "r"(a[2]), "r"(a[3]), "r"(b0), "r"(b1));
}

// Pre-pass: RNA-round W to tf32 once per launch.
__global__ void cvt_w_kernel(const float* __restrict__ W) {
    int i = blockIdx.x * blockDim.x + threadIdx.x;   // float4 index
    float4 v = reinterpret_cast<const float4*>(W)[i];
    v.x = __uint_as_float(f2tf(v.x));
    v.y = __uint_as_float(f2tf(v.y));
    v.z = __uint_as_float(f2tf(v.z));
    v.w = __uint_as_float(f2tf(v.w));
    reinterpret_cast<float4*>(g_Wtf)[i] = v;
}

__global__ void __launch_bounds__(256, 2)
mixed_conv_kernel(const float* __restrict__ x, const int* __restrict__ arcp,
                  const float* __restrict__ bias, float* __restrict__ out)
{
    extern __shared__ __align__(16) char smem_raw[];
    const uint32_t base = (smem_u32(smem_raw) + 1023) & ~1023u;
    const uint32_t sA[2] = { base,          base + 16384 };
    const uint32_t sB[2] = { base + 32768,  base + 49152 };

    const int tid = threadIdx.x;
    const int wid = tid >> 5, lid = tid & 31;
    const int wm  = wid >> 1;            // 0..3 -> co subtile (32 rows)
    const int wn  = wid & 1;             // 0..1 -> pixel subtile (64 cols)
    const int bid = blockIdx.x;
    const int b   = bid >> 4;
    const int co0 = ((bid >> 3) & 1) * 128;
    const int n0  = (bid & 7) * 128;
    const int arc = __ldg(arcp + b);

    const float* xb = x + (size_t)b * 262144;                 // 256*1024
    const float* Wb = g_Wtf + (size_t)arc * (256 * 2304) + (size_t)co0 * 2304;

    // B-fill geometry: thread t handles pixel p = t&127, k-half = t>>7
    const int p     = tid & 127;
    const int khalf = tid >> 7;
    const int pg    = n0 + p;
    const int h     = pg >> 5;
    const int w     = pg & 31;

    // ldmatrix per-lane sub decomposition
    const int rsubA = ((lid >> 3) & 1) * 8 + (lid & 7);
    const int csubA = ((lid >> 4) & 1) * 16;
    const int rsubB = ((lid >> 4) & 1) * 8 + (lid & 7);
    const int csubB = ((lid >> 3) & 1) * 16;
    int rowA[2], rselA[2], rowB[4], rselB[4];
    #pragma unroll
    for (int mi = 0; mi < 2; mi++) {
        rowA[mi]  = wm * 32 + mi * 16 + rsubA;
        rselA[mi] = (rowA[mi] & 7) << 4;
    }
    #pragma unroll
    for (int jj = 0; jj < 4; jj++) {
        rowB[jj]  = wn * 64 + jj * 16 + rsubB;
        rselB[jj] = (rowB[jj] & 7) << 4;
    }

    float acc[2][8][4];
    #pragma unroll
    for (int mi = 0; mi < 2; mi++)
        #pragma unroll
        for (int ni = 0; ni < 8; ni++)
            #pragma unroll
            for (int e = 0; e < 4; e++) acc[mi][ni][e] = 0.0f;

    // ---- helpers as lambdas -------------------------------------------------
    auto issueA = [&](int chunk, int s) {            // cp.async W tile -> sA[s]
        const int k0 = chunk * 32;
        #pragma unroll
        for (int m = 0; m < 4; m++) {
            const int c = tid + 256 * m;
            const int r = c >> 3, q = c & 7;
            cp16(sA[s] + SWZ(r * 128 + q * 16), Wb + r * 2304 + k0 + q * 4);
        }
    };
    auto loadB = [&](int chunk, float* rB) {         // im2col gather -> regs
        const int k0 = chunk * 32 + khalf * 16;
        #pragma unroll
        for (int e = 0; e < 16; e++) {
            const int k  = k0 + e;
            const int ci = (k * 7282) >> 16;         // k/9 (k < 2304)
            const int t9 = k - ci * 9;
            const int dh = ((t9 * 11) >> 5) - 1;     // t9/3 - 1
            const int dw = t9 - (dh + 1) * 3 - 1;    // t9%3 - 1
            float v = 0.0f;
            if ((unsigned)(h + dh) < 32u && (unsigned)(w + dw) < 32u)
                v = __ldg(xb + ci * 1024 + (h + dh) * 32 + (w + dw));
            rB[e] = v;
        }
    };
    auto storeB = [&](const float* rB, int s) {      // cvt + STS.128
        #pragma unroll
        for (int q = 0; q < 4; q++) {
            const int kc = khalf * 16 + q * 4;
            sts128(sB[s] + SWZ(p * 128 + kc * 4),
                   f2tf(rB[q * 4 + 0]), f2tf(rB[q * 4 + 1]),
                   f2tf(rB[q * 4 + 2]), f2tf(rB[q * 4 + 3]));
        }
    };

    // ---- prologue: stage chunk 0 -------------------------------------------
    issueA(0, 0);
    asm volatile("cp.async.commit_group;" ::: "memory");
    {
        float rB0[16];
        loadB(0, rB0);
        storeB(rB0, 0);
    }

    // ---- main loop ----------------------------------------------------------
    for (int i = 0; i < NCH; i++) {
        const int s  = i & 1;
        const int ns = s ^ 1;
        float rB[16];
        if (i + 1 < NCH) {
            issueA(i + 1, ns);
            asm volatile("cp.async.commit_group;" ::: "memory");
            loadB(i + 1, rB);
            asm volatile("cp.async.wait_group 1;" ::: "memory");
        } else {
            asm volatile("cp.async.wait_group 0;" ::: "memory");
        }
        __syncthreads();      // A[s] + B[s] ready & visible to all warps

        const uint32_t sAb = sA[s], sBb = sB[s];
        #pragma unroll
        for (int ks = 0; ks < 4; ks++) {
            uint32_t a[2][4];
            #pragma unroll
            for (int mi = 0; mi < 2; mi++)
                ldsm4(a[mi][0], a[mi][1], a[mi][2], a[mi][3],
                      sAb + rowA[mi] * 128 + ((ks * 32 + csubA) ^ rselA[mi]));
            #pragma unroll
            for (int jj = 0; jj < 4; jj++) {
                uint32_t b0, b1, b2, b3;
                ldsm4(b0, b1, b2, b3,
                      sBb + rowB[jj] * 128 + ((ks * 32 + csubB) ^ rselB[jj]));
                mma8(acc[0][2 * jj + 0], a[0], b0, b1);
                mma8(acc[0][2 * jj + 1], a[0], b2, b3);
                mma8(acc[1][2 * jj + 0], a[1], b0, b1);
                mma8(acc[1][2 * jj + 1], a[1], b2, b3);
            }
        }
        __syncthreads();      // all warps done reading stage s
        if (i + 1 < NCH) storeB(rB, ns);
        // visibility of this STS (and safety of next cp.async) is provided by
        // the wait+sync at the top of the next iteration / compute done above
    }

    // ---- epilogue: bias + store --------------------------------------------
    const int g = lid >> 2, t = lid & 3;
    #pragma unroll
    for (int mi = 0; mi < 2; mi++) {
        const int r0 = co0 + wm * 32 + mi * 16 + g;     // co of c0/c1
        const float bv0 = __ldg(bias + arc * 256 + r0);
        const float bv1 = __ldg(bias + arc * 256 + r0 + 8);
        float* o0 = out + ((size_t)(b * 256 + r0)) * 1024 + n0 + wn * 64 + 2 * t;
        float* o1 = o0 + 8 * 1024;
        #pragma unroll
        for (int ni = 0; ni < 8; ni++) {
            float2 v0 = { acc[mi][ni][0] + bv0, acc[mi][ni][1] + bv0 };
            float2 v1 = { acc[mi][ni][2] + bv1, acc[mi][ni][3] + bv1 };
            *reinterpret_cast<float2*>(o0 + ni * 8) = v0;
            *reinterpret_cast<float2*>(o1 + ni * 8) = v1;
        }
    }
}

extern "C" void kernel_launch(void* const* d_in, const int* in_sizes, int n_in,
                              void* d_out, int out_size) {
    const float* x    = (const float*)d_in[0];   // [64,256,32,32]
    const int*   arc  = (const int*)d_in[1];     // [64]
    const float* W    = (const float*)d_in[2];   // [4,256,256,3,3]
    const float* bias = (const float*)d_in[3];   // [4,256]
    float* out = (float*)d_out;                  // [64,256,32,32]
    (void)in_sizes; (void)n_in; (void)out_size;

    // 4*256*2304 floats / 4 per thread / 256 threads = 2304 blocks
    cvt_w_kernel<<<2304, 256>>>(W);

    cudaFuncSetAttribute(mixed_conv_kernel,
                         cudaFuncAttributeMaxDynamicSharedMemorySize, SMEM_BYTES);
    // 64 samples x 2 co-tiles x 8 pixel-tiles
    mixed_conv_kernel<<<1024, 256, SMEM_BYTES>>>(x, arc, bias, out);
}

// round 7
// speedup vs baseline: 2.1942x; 2.1942x over previous
#include <cuda_runtime.h>
#include <cuda_fp16.h>
#include <cstdint>

// ---------------------------------------------------------------------------
// MixedLayerWithArc: per-sample branch-selected 3x3 conv as implicit GEMM
// using mma.sync.m16n8k16 fp16 (fp32 accum). K order is TAP-MAJOR:
// k = tap*256 + ci, so each 64-wide k-chunk has a fixed (dh,dw) tap ->
// one halo predicate + strided loads for the whole chunk.
//
// Pre-pass converts W [4][256co][256ci][9tap] f32 -> g_Wh [4][256co][9][256ci]
// fp16 once per launch. fp16 mantissa == tf32 mantissa -> rel_err ~3e-4.
// ---------------------------------------------------------------------------

static constexpr int KTOT = 2304;                      // 9 taps * 256 ci
static constexpr int NCH  = KTOT / 64;                 // 36 chunks of BK=64
static constexpr int SMEM_BYTES = 1024 + 4 * 16384;    // pad + 2x(A16K+B16K)

// fp16 tap-major weights: [4][256][9][256]
__device__ __align__(16) __half g_Wh[4 * 256 * 2304];

#define SWZ(o) ((o) ^ (((o) >> 3) & 0x70))

__device__ __forceinline__ uint32_t smem_u32(const void* p) {
    uint32_t a;
    asm("{ .reg .u64 t; cvta.to.shared.u64 t, %1; cvt.u32.u64 %0, t; }"
        : "=r"(a) : "l"(p));
    return a;
}
__device__ __forceinline__ uint32_t pack_h2(float lo, float hi) {
    uint32_t u;
    asm("cvt.rn.f16x2.f32 %0, %1, %2;" : "=r"(u) : "f"(hi), "f"(lo));
    return u;
}
__device__ __forceinline__ void cp16(uint32_t dst, const void* src) {
    asm volatile("cp.async.cg.shared.global [%0], [%1], 16;"
                 :: "r"(dst), "l"(src) : "memory");
}
__device__ __forceinline__ void sts128(uint32_t a, uint32_t v0, uint32_t v1,
                                       uint32_t v2, uint32_t v3) {
    asm volatile("st.shared.v4.b32 [%0], {%1,%2,%3,%4};"
                 :: "r"(a), "r"(v0), "r"(v1), "r"(v2), "r"(v3) : "memory");
}
__device__ __forceinline__ void ldsm4(uint32_t& r0, uint32_t& r1, uint32_t& r2,
                                      uint32_t& r3, uint32_t a) {
    asm volatile("ldmatrix.sync.aligned.m8n8.x4.shared.b16 {%0,%1,%2,%3}, [%4];"
                 : "=r"(r0), "=r"(r1), "=r"(r2), "=r"(r3) : "r"(a));
}
__device__ __forceinline__ void mma16(float* c, const uint32_t* a,
                                      uint32_t b0, uint32_t b1) {
    asm volatile(
        "mma.sync.aligned.m16n8k16.row.col.f32.f16.f16.f32 "
        "{%0,%1,%2,%3}, {%4,%5,%6,%7}, {%8,%9}, {%0,%1,%2,%3};"
        : "+f"(c[0]), "+f"(c[1]), "+f"(c[2]), "+f"(c[3])
        : "r"(a[0]), "r"(a[1]), "r"(a[2]), "r"(a[3]), "r"(b0), "r"(b1));
}

// Pre-pass: W [arc*co][ci][tap] f32 -> g_Wh [arc*co][tap][ci] fp16.
__global__ void cvt_w_kernel(const float* __restrict__ W) {
    const int o    = blockIdx.x * 256 + threadIdx.x;   // output index
    const int ci   = o & 255;
    const int r    = o >> 8;            // (arc*256+co)*9 + tap
    const int tap  = r - (r / 9) * 9;
    const int acoc = r / 9;
    g_Wh[o] = __float2half_rn(W[(acoc * 256 + ci) * 9 + tap]);
}

__global__ void __launch_bounds__(256, 2)
mixed_conv_kernel(const float* __restrict__ x, const int* __restrict__ arcp,
                  const float* __restrict__ bias, float* __restrict__ out)
{
    extern __shared__ __align__(16) char smem_raw[];
    const uint32_t base = (smem_u32(smem_raw) + 1023) & ~1023u;
    const uint32_t sA[2] = { base,          base + 16384 };
    const uint32_t sB[2] = { base + 32768,  base + 49152 };

    const int tid = threadIdx.x;
    const int wid = tid >> 5, lid = tid & 31;
    const int wm  = wid >> 1;            // 0..3 -> 32 co rows
    const int wn  = wid & 1;             // 0..1 -> 64 pixel cols
    const int bid = blockIdx.x;
    const int b   = bid >> 4;
    const int co0 = ((bid >> 3) & 1) * 128;
    const int n0  = (bid & 7) * 128;
    const int arc = __ldg(arcp + b);

    const float*  xb = x + (size_t)b * 262144;                      // 256*1024
    const __half* Wb = g_Wh + (size_t)arc * (256 * 2304) + (size_t)co0 * 2304;

    // B-fill geometry: thread t -> pixel p = t&127, k-half (32 ci) = t>>7
    const int p     = tid & 127;
    const int khalf = tid >> 7;
    const int pg    = n0 + p;
    const int h     = pg >> 5;
    const int w     = pg & 31;

    // ldmatrix per-lane decomposition (identical byte math to validated tf32 ver)
    const int rsubA = lid & 15;
    const int csubA = ((lid >> 4) & 1) * 16;
    const int rsubB = (lid & 7) + ((lid >> 4) & 1) * 8;
    const int csubB = ((lid >> 3) & 1) * 16;
    int rowA[2], rselA[2], rowB[4], rselB[4];
    #pragma unroll
    for (int mi = 0; mi < 2; mi++) {
        rowA[mi]  = wm * 32 + mi * 16 + rsubA;
        rselA[mi] = (rowA[mi] & 7) << 4;
    }
    #pragma unroll
    for (int jj = 0; jj < 4; jj++) {
        rowB[jj]  = wn * 64 + jj * 16 + rsubB;
        rselB[jj] = (rowB[jj] & 7) << 4;
    }

    float acc[2][8][4];
    #pragma unroll
    for (int mi = 0; mi < 2; mi++)
        #pragma unroll
        for (int ni = 0; ni < 8; ni++)
            #pragma unroll
            for (int e = 0; e < 4; e++) acc[mi][ni][e] = 0.0f;

    // ---- helpers ------------------------------------------------------------
    auto issueA = [&](int chunk, int s) {       // cp.async W tile -> sA[s]
        // chunk*64 fp16 offset == tap*256 + cq*64 in the [tap][ci] layout
        #pragma unroll
        for (int m = 0; m < 4; m++) {
            const int c = tid + 256 * m;
            const int r = c >> 3, q = c & 7;    // row, 16B-unit within 128B row
            cp16(sA[s] + SWZ(r * 128 + q * 16),
                 Wb + (size_t)r * 2304 + chunk * 64 + q * 8);
        }
    };
    auto loadB = [&](int chunk, uint32_t* u) {  // 32 ci values -> 16 half2
        const int tap = chunk >> 2;             // 4 chunks per tap
        const int dh  = tap / 3 - 1;
        const int dw  = tap - (dh + 1) * 3 - 1;
        const bool ok = ((unsigned)(h + dh) < 32u) && ((unsigned)(w + dw) < 32u);
        const float* src = xb + ((chunk & 3) * 64 + khalf * 32) * 1024
                              + (h + dh) * 32 + (w + dw);
        #pragma unroll
        for (int j = 0; j < 16; j++) {
            const float v0 = ok ? __ldg(src + (2 * j)     * 1024) : 0.0f;
            const float v1 = ok ? __ldg(src + (2 * j + 1) * 1024) : 0.0f;
            u[j] = pack_h2(v0, v1);
        }
    };
    auto storeB = [&](const uint32_t* u, int s) {   // 4x STS.128
        #pragma unroll
        for (int q = 0; q < 4; q++) {
            const uint32_t off = p * 128 + khalf * 64 + q * 16;
            sts128(sB[s] + SWZ(off), u[q * 4], u[q * 4 + 1],
                   u[q * 4 + 2], u[q * 4 + 3]);
        }
    };

    // ---- prologue: stage chunk 0 -------------------------------------------
    issueA(0, 0);
    asm volatile("cp.async.commit_group;" ::: "memory");
    {
        uint32_t u0[16];
        loadB(0, u0);
        storeB(u0, 0);
    }

    // ---- main loop ----------------------------------------------------------
    for (int i = 0; i < NCH; i++) {
        const int s  = i & 1;
        const int ns = s ^ 1;
        uint32_t u[16];
        if (i + 1 < NCH) {
            issueA(i + 1, ns);
            asm volatile("cp.async.commit_group;" ::: "memory");
            loadB(i + 1, u);
            asm volatile("cp.async.wait_group 1;" ::: "memory");
        } else {
            asm volatile("cp.async.wait_group 0;" ::: "memory");
        }
        __syncthreads();      // A[s] + B[s] ready & visible

        const uint32_t sAb = sA[s], sBb = sB[s];
        #pragma unroll
        for (int ks = 0; ks < 4; ks++) {        // 4 x k16 steps (32B each)
            uint32_t a[2][4];
            #pragma unroll
            for (int mi = 0; mi < 2; mi++)
                ldsm4(a[mi][0], a[mi][1], a[mi][2], a[mi][3],
                      sAb + rowA[mi] * 128 + ((ks * 32 + csubA) ^ rselA[mi]));
            #pragma unroll
            for (int jj = 0; jj < 4; jj++) {
                uint32_t b0, b1, b2, b3;
                ldsm4(b0, b1, b2, b3,
                      sBb + rowB[jj] * 128 + ((ks * 32 + csubB) ^ rselB[jj]));
                mma16(acc[0][2 * jj + 0], a[0], b0, b1);
                mma16(acc[0][2 * jj + 1], a[0], b2, b3);
                mma16(acc[1][2 * jj + 0], a[1], b0, b1);
                mma16(acc[1][2 * jj + 1], a[1], b2, b3);
            }
        }
        __syncthreads();      // all warps done with stage s
        if (i + 1 < NCH) storeB(u, ns);
    }

    // ---- epilogue: bias + store --------------------------------------------
    const int g = lid >> 2, t = lid & 3;
    #pragma unroll
    for (int mi = 0; mi < 2; mi++) {
        const int r0 = co0 + wm * 32 + mi * 16 + g;
        const float bv0 = __ldg(bias + arc * 256 + r0);
        const float bv1 = __ldg(bias + arc * 256 + r0 + 8);
        float* o0 = out + ((size_t)(b * 256 + r0)) * 1024 + n0 + wn * 64 + 2 * t;
        float* o1 = o0 + 8 * 1024;
        #pragma unroll
        for (int ni = 0; ni < 8; ni++) {
            float2 v0 = { acc[mi][ni][0] + bv0, acc[mi][ni][1] + bv0 };
            float2 v1 = { acc[mi][ni][2] + bv1, acc[mi][ni][3] + bv1 };
            *reinterpret_cast<float2*>(o0 + ni * 8) = v0;
            *reinterpret_cast<float2*>(o1 + ni * 8) = v1;
        }
    }
}

extern "C" void kernel_launch(void* const* d_in, const int* in_sizes, int n_in,
                              void* d_out, int out_size) {
    const float* x    = (const float*)d_in[0];   // [64,256,32,32]
    const int*   arc  = (const int*)d_in[1];     // [64]
    const float* W    = (const float*)d_in[2];   // [4,256,256,3,3]
    const float* bias = (const float*)d_in[3];   // [4,256]
    float* out = (float*)d_out;                  // [64,256,32,32]
    (void)in_sizes; (void)n_in; (void)out_size;

    // 4*256*2304 = 2,359,296 elements / 256 threads = 9216 blocks
    cvt_w_kernel<<<9216, 256>>>(W);

    cudaFuncSetAttribute(mixed_conv_kernel,
                         cudaFuncAttributeMaxDynamicSharedMemorySize, SMEM_BYTES);
    // 64 samples x 2 co-tiles x 8 pixel-tiles
    mixed_conv_kernel<<<1024, 256, SMEM_BYTES>>>(x, arc, bias, out);
}